// round 15
// baseline (speedup 1.0000x reference)
#include <cuda_runtime.h>

#define A_NUM 5
#define EPSV 1e-10f

// ---------------- parameter block: device-computed, constant-consumed ------
struct Params {
    float4 Q4[48];   // Qt rows (16 float4), G rows (16), Qy rows (16)
    float  wr[8];    // yt weights (padded)
    float  ws[8];    // st weights (padded)
    float  t;        // gate
    float  pad[3];
};

__constant__ Params c_params;

// ---------------- warp-parallel prologue ----------------
// Writes DIRECTLY into the __constant__ bank via its device address (pp).
// Constant caches are (re)loaded at each kernel launch, so the main kernel —
// launched after this one on the same stream — sees the updated values.
// Lanes 0-7: Qr, lanes 8-15: Qt, lanes 16-23: Qy. Each lane owns one row of
// the augmented system [I-Bm | I+Bm]; Gauss-Jordan with partial pivoting via
// width-8 shuffles (no row swaps; pivot permutation tracked per-lane).
__global__ void spdsru_prologue(Params* __restrict__ pp,
                                const float* __restrict__ kr,
                                const float* __restrict__ kt,
                                const float* __restrict__ kphi,
                                const float* __restrict__ ks,
                                const float* __restrict__ br,
                                const float* __restrict__ bt,
                                const float* __restrict__ by) {
    __shared__ float sQ[3][64];   // Qr, Qt, Qy row-major

    const int tid = threadIdx.x;
    float* Qflat = reinterpret_cast<float*>(pp->Q4);

    if (tid < 24) {
        const int g = tid >> 3;        // matrix group 0..2
        const int r = tid & 7;         // my row
        const unsigned mask = 0xFFu << (g * 8);
        const float* bias = (g == 0) ? br : ((g == 1) ? bt : by);

        // Row r of Bm = L - L^T with L[i+1][c] = b[i+c], c in [0, i].
        float a[16];
#pragma unroll
        for (int j = 0; j < 16; j++) a[j] = 0.0f;
        for (int j = 0; j < 8; j++) {
            float bm = 0.0f;
            if (j < r)      bm = bias[r - 1 + j];        // L
            else if (j > r) bm = -bias[j - 1 + r];       // -L^T
            float d = (j == r) ? 1.0f : 0.0f;
            a[j]     = d - bm;   // I - Bm
            a[j + 8] = d + bm;   // I + Bm
        }

        // Gauss-Jordan, partial pivoting, no swaps.
        bool used = false;
        int myk = -1;
        for (int k = 0; k < 8; k++) {
            float v = used ? -1.0f : fabsf(a[k]);
            int idx = r;
#pragma unroll
            for (int off = 4; off > 0; off >>= 1) {
                float ov = __shfl_xor_sync(mask, v, off, 8);
                int   oi = __shfl_xor_sync(mask, idx, off, 8);
                if (ov > v || (ov == v && oi < idx)) { v = ov; idx = oi; }
            }
            const int p = idx;
            const float piv = __shfl_sync(mask, a[k], p, 8);
            const float invpiv = 1.0f / piv;
            const bool ispiv = (r == p);
            const float f = a[k];
#pragma unroll
            for (int j = 0; j < 16; j++) {
                float pj = __shfl_sync(mask, a[j], p, 8) * invpiv;
                a[j] = ispiv ? pj : fmaf(-f, pj, a[j]);
            }
            if (ispiv) { used = true; myk = k; }
        }

        for (int j = 0; j < 8; j++) sQ[g][myk * 8 + j] = a[8 + j];
    }
    __syncthreads();

    if (tid < 64) {
        // copy Qt, Qy; compute G = Qt @ Qr (one element per thread)
        Qflat[tid]       = sQ[1][tid];   // Qt
        Qflat[128 + tid] = sQ[2][tid];   // Qy
        const int i = tid >> 3, j = tid & 7;
        float s = 0.0f;
#pragma unroll
        for (int k = 0; k < 8; k++) s += sQ[1][i * 8 + k] * sQ[0][k * 8 + j];
        Qflat[64 + tid] = s;             // G
    } else if (tid == 64) {
        float r2[A_NUM], s2[A_NUM], sr = 0.0f, ss = 0.0f;
        for (int a = 0; a < A_NUM; a++) {
            r2[a] = kr[a] * kr[a]; sr += r2[a];
            s2[a] = ks[a] * ks[a]; ss += s2[a];
        }
        float ir = 1.0f / (sr + EPSV);
        float is = 1.0f / (ss + EPSV);
        for (int a = 0; a < 8; a++) { pp->wr[a] = 0.0f; pp->ws[a] = 0.0f; }
        for (int a = 0; a < A_NUM; a++) {
            pp->wr[a] = r2[a] * ir;
            pp->ws[a] = s2[a] * is;
        }
        float t2 = kt[0] * kt[0];
        pp->t = t2 / (t2 + kphi[0] * kphi[0] + EPSV);
    }
}

// ---------------- main streaming kernel (converged design) -----------------
// 128 threads/block = 16 batch elements; thread j of each 8-thread group owns
// row j of every 8x8 matrix. States stay REGISTER-RESIDENT (one global read,
// one global write; default cache policy — L2 allocate helps here).
// Congruence C = Q*A*Q^T:
//   stage 1: B_row_j = A_row_j * Q^T   (Q rows from CONSTANT memory -> LDC,
//                                       off the L1tex pipe)
//   stage 2: row j -> sB (STS.128), syncwarp, gather via broadcast LDS.128
//            with Q[j][i] from smem padded array (scalar broadcast LDS).

template <int QB>   // base index into c_params.Q4 (float4 units)
__device__ __forceinline__ void congruence8(const float* a,
                                            const float* pQ,     // smem padded Q (stride 9)
                                            int j,
                                            float* bufbase,      // smem group tile (72 floats)
                                            float* c) {
    float bb[8];
#pragma unroll
    for (int k = 0; k < 8; k++) {
        float4 q0 = c_params.Q4[QB + 2 * k];
        float4 q1 = c_params.Q4[QB + 2 * k + 1];
        float s = a[0] * q0.x;
        s = fmaf(a[1], q0.y, s);
        s = fmaf(a[2], q0.z, s);
        s = fmaf(a[3], q0.w, s);
        s = fmaf(a[4], q1.x, s);
        s = fmaf(a[5], q1.y, s);
        s = fmaf(a[6], q1.z, s);
        s = fmaf(a[7], q1.w, s);
        bb[k] = s;
    }
    __syncwarp();   // prior reads of this buffer are done
    float4* bw = reinterpret_cast<float4*>(bufbase + j * 8);
    bw[0] = make_float4(bb[0], bb[1], bb[2], bb[3]);
    bw[1] = make_float4(bb[4], bb[5], bb[6], bb[7]);
    __syncwarp();   // all 8 rows visible before gathering
#pragma unroll
    for (int k = 0; k < 8; k++) c[k] = 0.0f;
#pragma unroll
    for (int i = 0; i < 8; i++) {
        float qji = pQ[j * 9 + i];
        const float4* br = reinterpret_cast<const float4*>(bufbase + i * 8);
        float4 b0 = br[0];
        float4 b1 = br[1];
        c[0] = fmaf(qji, b0.x, c[0]);
        c[1] = fmaf(qji, b0.y, c[1]);
        c[2] = fmaf(qji, b0.z, c[2]);
        c[3] = fmaf(qji, b0.w, c[3]);
        c[4] = fmaf(qji, b1.x, c[4]);
        c[5] = fmaf(qji, b1.y, c[5]);
        c[6] = fmaf(qji, b1.z, c[6]);
        c[7] = fmaf(qji, b1.w, c[7]);
    }
}

__global__ void __launch_bounds__(128)
spdsru_main(const float* __restrict__ x,
            const float* __restrict__ states,
            float* __restrict__ out,
            float* __restrict__ outst) {
    __shared__ float sP[3 * 72];    // padded Qt | G | Qy (stride 9)
    __shared__ float sB[16 * 72];   // congruence scratch (4 warps * 4 groups)

    const int tid = threadIdx.x;
    if (tid < 64) {
        int r = tid >> 3, cc = tid & 7;
        const float* cf = reinterpret_cast<const float*>(c_params.Q4);
        sP[r * 9 + cc]       = cf[tid];         // Qt
        sP[72 + r * 9 + cc]  = cf[64 + tid];    // G
        sP[144 + r * 9 + cc] = cf[128 + tid];   // Qy
    }
    __syncthreads();

    const int grp = tid >> 3;            // 0..15
    const int j = tid & 7;
    const size_t b = (size_t)blockIdx.x * 16 + grp;
    float* bufbase = sB + grp * 72;

    // ---- load x row ----
    const float4* xp = reinterpret_cast<const float4*>(x + b * 64 + j * 8);
    float4 xa = xp[0], xb = xp[1];
    float xr[8] = {xa.x, xa.y, xa.z, xa.w, xb.x, xb.y, xb.z, xb.w};

    // ---- load state rows (register-resident), accumulate Yt in-flight ----
    float m[A_NUM][8];
    float yt[8];
#pragma unroll
    for (int k = 0; k < 8; k++) yt[k] = 0.0f;
#pragma unroll
    for (int a = 0; a < A_NUM; a++) {
        const float4* mp = reinterpret_cast<const float4*>(states + b * 320 + a * 64 + j * 8);
        float4 m0 = mp[0], m1 = mp[1];
        m[a][0] = m0.x; m[a][1] = m0.y; m[a][2] = m0.z; m[a][3] = m0.w;
        m[a][4] = m1.x; m[a][5] = m1.y; m[a][6] = m1.z; m[a][7] = m1.w;
        float wa = c_params.wr[a];
#pragma unroll
        for (int k = 0; k < 8; k++) yt[k] = fmaf(wa, m[a][k], yt[k]);
    }

    // ---- U = Qt*Xt*Qt^T ;  V = G*Yt*G^T  (G = Qt*Qr) ----
    float u[8], v[8];
    congruence8<0>(xr, sP, j, bufbase, u);
    congruence8<16>(yt, sP + 72, j, bufbase, v);

    // ---- Phit = (1-t)*U + t*V ----
    const float t = c_params.t;
    float phit[8];
#pragma unroll
    for (int k = 0; k < 8; k++) phit[k] = fmaf(t, v[k] - u[k], u[k]);

    // ---- Mt[a] = m + alpha*(Phit - m) ; St = sum ws[a]*Mt[a] ; write Mt ----
    const float alpha[A_NUM] = {0.01f, 0.25f, 0.5f, 0.9f, 0.99f};
    float st[8];
#pragma unroll
    for (int k = 0; k < 8; k++) st[k] = 0.0f;
#pragma unroll
    for (int a = 0; a < A_NUM; a++) {
        float mt[8];
        float wsa = c_params.ws[a];
#pragma unroll
        for (int k = 0; k < 8; k++) {
            mt[k] = fmaf(alpha[a], phit[k] - m[a][k], m[a][k]);
            st[k] = fmaf(wsa, mt[k], st[k]);
        }
        float4* op = reinterpret_cast<float4*>(outst + b * 320 + a * 64 + j * 8);
        op[0] = make_float4(mt[0], mt[1], mt[2], mt[3]);
        op[1] = make_float4(mt[4], mt[5], mt[6], mt[7]);
    }

    // ---- Ot = Qy * St * Qy^T ----
    float ot[8];
    congruence8<32>(st, sP + 144, j, bufbase, ot);
    float4* oo = reinterpret_cast<float4*>(out + b * 64 + j * 8);
    oo[0] = make_float4(ot[0], ot[1], ot[2], ot[3]);
    oo[1] = make_float4(ot[4], ot[5], ot[6], ot[7]);
}

extern "C" void kernel_launch(void* const* d_in, const int* in_sizes, int n_in,
                              void* d_out, int out_size) {
    const float* x      = (const float*)d_in[0];
    const float* states = (const float*)d_in[1];
    const float* kr     = (const float*)d_in[2];
    const float* kt     = (const float*)d_in[3];
    const float* kphi   = (const float*)d_in[4];
    const float* ks     = (const float*)d_in[5];
    const float* br     = (const float*)d_in[6];
    const float* bt     = (const float*)d_in[7];
    const float* by     = (const float*)d_in[8];

    const int batch = in_sizes[0] / 64;

    float* out   = (float*)d_out;
    float* outst = out + (size_t)batch * 64;

    // Device address of the __constant__ block — prologue writes it directly;
    // the main kernel's constant cache is loaded fresh at its own launch.
    void* csym = nullptr;
    cudaGetSymbolAddress(&csym, c_params);

    spdsru_prologue<<<1, 128>>>((Params*)csym, kr, kt, kphi, ks, br, bt, by);

    int blocks = batch / 16;
    spdsru_main<<<blocks, 128>>>(x, states, out, outst);
}

// round 16
// speedup vs baseline: 1.0015x; 1.0015x over previous
#include <cuda_runtime.h>

#define A_NUM 5
#define EPSV 1e-10f

// ---------------- parameter block: device-computed, constant-consumed ------
struct Params {
    float4 Q4[48];   // Qt rows (16 float4), G rows (16), Qy rows (16)
    float  wr[8];    // yt weights (padded)
    float  ws[8];    // st weights (padded)
    float  t;        // gate
    float  pad[3];
};

__constant__ Params c_params;

// ---------------- warp-parallel prologue ----------------
// Writes DIRECTLY into the __constant__ bank via its device address (pp).
// Constant caches are (re)loaded at each kernel launch, so the main kernel —
// launched after this one on the same stream — sees the updated values.
// Lanes 0-7: Qr, lanes 8-15: Qt, lanes 16-23: Qy. Each lane owns one row of
// the augmented system [I-Bm | I+Bm]; Gauss-Jordan with partial pivoting via
// width-8 shuffles (no row swaps; pivot permutation tracked per-lane).
__global__ void spdsru_prologue(Params* __restrict__ pp,
                                const float* __restrict__ kr,
                                const float* __restrict__ kt,
                                const float* __restrict__ kphi,
                                const float* __restrict__ ks,
                                const float* __restrict__ br,
                                const float* __restrict__ bt,
                                const float* __restrict__ by) {
    __shared__ float sQ[3][64];   // Qr, Qt, Qy row-major

    const int tid = threadIdx.x;
    float* Qflat = reinterpret_cast<float*>(pp->Q4);

    if (tid < 24) {
        const int g = tid >> 3;        // matrix group 0..2
        const int r = tid & 7;         // my row
        const unsigned mask = 0xFFu << (g * 8);
        const float* bias = (g == 0) ? br : ((g == 1) ? bt : by);

        // Row r of Bm = L - L^T with L[i+1][c] = b[i+c], c in [0, i].
        float a[16];
#pragma unroll
        for (int j = 0; j < 16; j++) a[j] = 0.0f;
        for (int j = 0; j < 8; j++) {
            float bm = 0.0f;
            if (j < r)      bm = bias[r - 1 + j];        // L
            else if (j > r) bm = -bias[j - 1 + r];       // -L^T
            float d = (j == r) ? 1.0f : 0.0f;
            a[j]     = d - bm;   // I - Bm
            a[j + 8] = d + bm;   // I + Bm
        }

        // Gauss-Jordan, partial pivoting, no swaps.
        bool used = false;
        int myk = -1;
        for (int k = 0; k < 8; k++) {
            float v = used ? -1.0f : fabsf(a[k]);
            int idx = r;
#pragma unroll
            for (int off = 4; off > 0; off >>= 1) {
                float ov = __shfl_xor_sync(mask, v, off, 8);
                int   oi = __shfl_xor_sync(mask, idx, off, 8);
                if (ov > v || (ov == v && oi < idx)) { v = ov; idx = oi; }
            }
            const int p = idx;
            const float piv = __shfl_sync(mask, a[k], p, 8);
            const float invpiv = 1.0f / piv;
            const bool ispiv = (r == p);
            const float f = a[k];
#pragma unroll
            for (int j = 0; j < 16; j++) {
                float pj = __shfl_sync(mask, a[j], p, 8) * invpiv;
                a[j] = ispiv ? pj : fmaf(-f, pj, a[j]);
            }
            if (ispiv) { used = true; myk = k; }
        }

        for (int j = 0; j < 8; j++) sQ[g][myk * 8 + j] = a[8 + j];
    }
    __syncthreads();

    if (tid < 64) {
        // copy Qt, Qy; compute G = Qt @ Qr (one element per thread)
        Qflat[tid]       = sQ[1][tid];   // Qt
        Qflat[128 + tid] = sQ[2][tid];   // Qy
        const int i = tid >> 3, j = tid & 7;
        float s = 0.0f;
#pragma unroll
        for (int k = 0; k < 8; k++) s += sQ[1][i * 8 + k] * sQ[0][k * 8 + j];
        Qflat[64 + tid] = s;             // G
    } else if (tid == 64) {
        float r2[A_NUM], s2[A_NUM], sr = 0.0f, ss = 0.0f;
        for (int a = 0; a < A_NUM; a++) {
            r2[a] = kr[a] * kr[a]; sr += r2[a];
            s2[a] = ks[a] * ks[a]; ss += s2[a];
        }
        float ir = 1.0f / (sr + EPSV);
        float is = 1.0f / (ss + EPSV);
        for (int a = 0; a < 8; a++) { pp->wr[a] = 0.0f; pp->ws[a] = 0.0f; }
        for (int a = 0; a < A_NUM; a++) {
            pp->wr[a] = r2[a] * ir;
            pp->ws[a] = s2[a] * is;
        }
        float t2 = kt[0] * kt[0];
        pp->t = t2 / (t2 + kphi[0] * kphi[0] + EPSV);
    }
}

// ---------------- main streaming kernel (converged design) -----------------
// 128 threads/block = 16 batch elements; thread j of each 8-thread group owns
// row j of every 8x8 matrix. States stay REGISTER-RESIDENT (one global read,
// one global write; default cache policy — L2 allocate helps here).
// Congruence C = Q*A*Q^T:
//   stage 1: B_row_j = A_row_j * Q^T   (Q rows from CONSTANT memory -> LDC,
//                                       off the L1tex pipe)
//   stage 2: row j -> sB (STS.128), syncwarp, gather via broadcast LDS.128
//            with Q[j][i] from smem padded array (scalar broadcast LDS).

template <int QB>   // base index into c_params.Q4 (float4 units)
__device__ __forceinline__ void congruence8(const float* a,
                                            const float* pQ,     // smem padded Q (stride 9)
                                            int j,
                                            float* bufbase,      // smem group tile (72 floats)
                                            float* c) {
    float bb[8];
#pragma unroll
    for (int k = 0; k < 8; k++) {
        float4 q0 = c_params.Q4[QB + 2 * k];
        float4 q1 = c_params.Q4[QB + 2 * k + 1];
        float s = a[0] * q0.x;
        s = fmaf(a[1], q0.y, s);
        s = fmaf(a[2], q0.z, s);
        s = fmaf(a[3], q0.w, s);
        s = fmaf(a[4], q1.x, s);
        s = fmaf(a[5], q1.y, s);
        s = fmaf(a[6], q1.z, s);
        s = fmaf(a[7], q1.w, s);
        bb[k] = s;
    }
    __syncwarp();   // prior reads of this buffer are done
    float4* bw = reinterpret_cast<float4*>(bufbase + j * 8);
    bw[0] = make_float4(bb[0], bb[1], bb[2], bb[3]);
    bw[1] = make_float4(bb[4], bb[5], bb[6], bb[7]);
    __syncwarp();   // all 8 rows visible before gathering
#pragma unroll
    for (int k = 0; k < 8; k++) c[k] = 0.0f;
#pragma unroll
    for (int i = 0; i < 8; i++) {
        float qji = pQ[j * 9 + i];
        const float4* br = reinterpret_cast<const float4*>(bufbase + i * 8);
        float4 b0 = br[0];
        float4 b1 = br[1];
        c[0] = fmaf(qji, b0.x, c[0]);
        c[1] = fmaf(qji, b0.y, c[1]);
        c[2] = fmaf(qji, b0.z, c[2]);
        c[3] = fmaf(qji, b0.w, c[3]);
        c[4] = fmaf(qji, b1.x, c[4]);
        c[5] = fmaf(qji, b1.y, c[5]);
        c[6] = fmaf(qji, b1.z, c[6]);
        c[7] = fmaf(qji, b1.w, c[7]);
    }
}

__global__ void __launch_bounds__(128)
spdsru_main(const float* __restrict__ x,
            const float* __restrict__ states,
            float* __restrict__ out,
            float* __restrict__ outst) {
    __shared__ float sP[3 * 72];    // padded Qt | G | Qy (stride 9)
    __shared__ float sB[16 * 72];   // congruence scratch (4 warps * 4 groups)

    const int tid = threadIdx.x;
    if (tid < 64) {
        int r = tid >> 3, cc = tid & 7;
        const float* cf = reinterpret_cast<const float*>(c_params.Q4);
        sP[r * 9 + cc]       = cf[tid];         // Qt
        sP[72 + r * 9 + cc]  = cf[64 + tid];    // G
        sP[144 + r * 9 + cc] = cf[128 + tid];   // Qy
    }
    __syncthreads();

    const int grp = tid >> 3;            // 0..15
    const int j = tid & 7;
    const size_t b = (size_t)blockIdx.x * 16 + grp;
    float* bufbase = sB + grp * 72;

    // ---- load x row ----
    const float4* xp = reinterpret_cast<const float4*>(x + b * 64 + j * 8);
    float4 xa = xp[0], xb = xp[1];
    float xr[8] = {xa.x, xa.y, xa.z, xa.w, xb.x, xb.y, xb.z, xb.w};

    // ---- load state rows (register-resident), accumulate Yt in-flight ----
    float m[A_NUM][8];
    float yt[8];
#pragma unroll
    for (int k = 0; k < 8; k++) yt[k] = 0.0f;
#pragma unroll
    for (int a = 0; a < A_NUM; a++) {
        const float4* mp = reinterpret_cast<const float4*>(states + b * 320 + a * 64 + j * 8);
        float4 m0 = mp[0], m1 = mp[1];
        m[a][0] = m0.x; m[a][1] = m0.y; m[a][2] = m0.z; m[a][3] = m0.w;
        m[a][4] = m1.x; m[a][5] = m1.y; m[a][6] = m1.z; m[a][7] = m1.w;
        float wa = c_params.wr[a];
#pragma unroll
        for (int k = 0; k < 8; k++) yt[k] = fmaf(wa, m[a][k], yt[k]);
    }

    // ---- U = Qt*Xt*Qt^T ;  V = G*Yt*G^T  (G = Qt*Qr) ----
    float u[8], v[8];
    congruence8<0>(xr, sP, j, bufbase, u);
    congruence8<16>(yt, sP + 72, j, bufbase, v);

    // ---- Phit = (1-t)*U + t*V ----
    const float t = c_params.t;
    float phit[8];
#pragma unroll
    for (int k = 0; k < 8; k++) phit[k] = fmaf(t, v[k] - u[k], u[k]);

    // ---- Mt[a] = m + alpha*(Phit - m) ; St = sum ws[a]*Mt[a] ; write Mt ----
    const float alpha[A_NUM] = {0.01f, 0.25f, 0.5f, 0.9f, 0.99f};
    float st[8];
#pragma unroll
    for (int k = 0; k < 8; k++) st[k] = 0.0f;
#pragma unroll
    for (int a = 0; a < A_NUM; a++) {
        float mt[8];
        float wsa = c_params.ws[a];
#pragma unroll
        for (int k = 0; k < 8; k++) {
            mt[k] = fmaf(alpha[a], phit[k] - m[a][k], m[a][k]);
            st[k] = fmaf(wsa, mt[k], st[k]);
        }
        float4* op = reinterpret_cast<float4*>(outst + b * 320 + a * 64 + j * 8);
        op[0] = make_float4(mt[0], mt[1], mt[2], mt[3]);
        op[1] = make_float4(mt[4], mt[5], mt[6], mt[7]);
    }

    // ---- Ot = Qy * St * Qy^T ----
    float ot[8];
    congruence8<32>(st, sP + 144, j, bufbase, ot);
    float4* oo = reinterpret_cast<float4*>(out + b * 64 + j * 8);
    oo[0] = make_float4(ot[0], ot[1], ot[2], ot[3]);
    oo[1] = make_float4(ot[4], ot[5], ot[6], ot[7]);
}

extern "C" void kernel_launch(void* const* d_in, const int* in_sizes, int n_in,
                              void* d_out, int out_size) {
    const float* x      = (const float*)d_in[0];
    const float* states = (const float*)d_in[1];
    const float* kr     = (const float*)d_in[2];
    const float* kt     = (const float*)d_in[3];
    const float* kphi   = (const float*)d_in[4];
    const float* ks     = (const float*)d_in[5];
    const float* br     = (const float*)d_in[6];
    const float* bt     = (const float*)d_in[7];
    const float* by     = (const float*)d_in[8];

    const int batch = in_sizes[0] / 64;

    float* out   = (float*)d_out;
    float* outst = out + (size_t)batch * 64;

    // Device address of the __constant__ block — prologue writes it directly;
    // the main kernel's constant cache is loaded fresh at its own launch.
    void* csym = nullptr;
    cudaGetSymbolAddress(&csym, c_params);

    spdsru_prologue<<<1, 128>>>((Params*)csym, kr, kt, kphi, ks, br, bt, by);

    int blocks = batch / 16;
    spdsru_main<<<blocks, 128>>>(x, states, out, outst);
}

// round 17
// speedup vs baseline: 1.0130x; 1.0115x over previous
#include <cuda_runtime.h>

#define A_NUM 5
#define EPSV 1e-10f

// ---------------- parameter block: device-computed, constant-consumed ------
struct Params {
    float4 Q4[48];   // Qt rows (16 float4), G rows (16), Qy rows (16)
    float  wr[8];    // yt weights (padded)
    float  ws[8];    // st weights (padded)
    float  t;        // gate
    float  pad[3];
};

__constant__ Params c_params;

// ---------------- warp-parallel prologue ----------------
// Writes DIRECTLY into the __constant__ bank via its device address (pp).
// Constant caches are (re)loaded at each kernel launch, so the main kernel —
// launched after this one on the same stream — sees the updated values.
// Lanes 0-7: Qr, lanes 8-15: Qt, lanes 16-23: Qy. Each lane owns one row of
// the augmented system [I-Bm | I+Bm]; Gauss-Jordan with partial pivoting via
// width-8 shuffles (no row swaps; pivot permutation tracked per-lane).
__global__ void spdsru_prologue(Params* __restrict__ pp,
                                const float* __restrict__ kr,
                                const float* __restrict__ kt,
                                const float* __restrict__ kphi,
                                const float* __restrict__ ks,
                                const float* __restrict__ br,
                                const float* __restrict__ bt,
                                const float* __restrict__ by) {
    __shared__ float sQ[3][64];   // Qr, Qt, Qy row-major

    const int tid = threadIdx.x;
    float* Qflat = reinterpret_cast<float*>(pp->Q4);

    if (tid < 24) {
        const int g = tid >> 3;        // matrix group 0..2
        const int r = tid & 7;         // my row
        const unsigned mask = 0xFFu << (g * 8);
        const float* bias = (g == 0) ? br : ((g == 1) ? bt : by);

        // Row r of Bm = L - L^T with L[i+1][c] = b[i+c], c in [0, i].
        float a[16];
#pragma unroll
        for (int j = 0; j < 16; j++) a[j] = 0.0f;
        for (int j = 0; j < 8; j++) {
            float bm = 0.0f;
            if (j < r)      bm = bias[r - 1 + j];        // L
            else if (j > r) bm = -bias[j - 1 + r];       // -L^T
            float d = (j == r) ? 1.0f : 0.0f;
            a[j]     = d - bm;   // I - Bm
            a[j + 8] = d + bm;   // I + Bm
        }

        // Gauss-Jordan, partial pivoting, no swaps.
        bool used = false;
        int myk = -1;
        for (int k = 0; k < 8; k++) {
            float v = used ? -1.0f : fabsf(a[k]);
            int idx = r;
#pragma unroll
            for (int off = 4; off > 0; off >>= 1) {
                float ov = __shfl_xor_sync(mask, v, off, 8);
                int   oi = __shfl_xor_sync(mask, idx, off, 8);
                if (ov > v || (ov == v && oi < idx)) { v = ov; idx = oi; }
            }
            const int p = idx;
            const float piv = __shfl_sync(mask, a[k], p, 8);
            const float invpiv = 1.0f / piv;
            const bool ispiv = (r == p);
            const float f = a[k];
#pragma unroll
            for (int j = 0; j < 16; j++) {
                float pj = __shfl_sync(mask, a[j], p, 8) * invpiv;
                a[j] = ispiv ? pj : fmaf(-f, pj, a[j]);
            }
            if (ispiv) { used = true; myk = k; }
        }

        for (int j = 0; j < 8; j++) sQ[g][myk * 8 + j] = a[8 + j];
    }
    __syncthreads();

    if (tid < 64) {
        // copy Qt, Qy; compute G = Qt @ Qr (one element per thread)
        Qflat[tid]       = sQ[1][tid];   // Qt
        Qflat[128 + tid] = sQ[2][tid];   // Qy
        const int i = tid >> 3, j = tid & 7;
        float s = 0.0f;
#pragma unroll
        for (int k = 0; k < 8; k++) s += sQ[1][i * 8 + k] * sQ[0][k * 8 + j];
        Qflat[64 + tid] = s;             // G
    } else if (tid == 64) {
        float r2[A_NUM], s2[A_NUM], sr = 0.0f, ss = 0.0f;
        for (int a = 0; a < A_NUM; a++) {
            r2[a] = kr[a] * kr[a]; sr += r2[a];
            s2[a] = ks[a] * ks[a]; ss += s2[a];
        }
        float ir = 1.0f / (sr + EPSV);
        float is = 1.0f / (ss + EPSV);
        for (int a = 0; a < 8; a++) { pp->wr[a] = 0.0f; pp->ws[a] = 0.0f; }
        for (int a = 0; a < A_NUM; a++) {
            pp->wr[a] = r2[a] * ir;
            pp->ws[a] = s2[a] * is;
        }
        float t2 = kt[0] * kt[0];
        pp->t = t2 / (t2 + kphi[0] * kphi[0] + EPSV);
    }
}

// ---------------- main streaming kernel (converged design) -----------------
// 128 threads/block = 16 batch elements; thread j of each 8-thread group owns
// row j of every 8x8 matrix. States stay REGISTER-RESIDENT (one global read,
// one global write; default cache policy — L2 allocate helps here).
// Congruence C = Q*A*Q^T:
//   stage 1: B_row_j = A_row_j * Q^T   (Q rows from CONSTANT memory -> LDC,
//                                       off the L1tex pipe)
//   stage 2: row j -> sB (STS.128), syncwarp, gather via broadcast LDS.128
//            with Q[j][i] from smem padded array (scalar broadcast LDS).

template <int QB>   // base index into c_params.Q4 (float4 units)
__device__ __forceinline__ void congruence8(const float* a,
                                            const float* pQ,     // smem padded Q (stride 9)
                                            int j,
                                            float* bufbase,      // smem group tile (72 floats)
                                            float* c) {
    float bb[8];
#pragma unroll
    for (int k = 0; k < 8; k++) {
        float4 q0 = c_params.Q4[QB + 2 * k];
        float4 q1 = c_params.Q4[QB + 2 * k + 1];
        float s = a[0] * q0.x;
        s = fmaf(a[1], q0.y, s);
        s = fmaf(a[2], q0.z, s);
        s = fmaf(a[3], q0.w, s);
        s = fmaf(a[4], q1.x, s);
        s = fmaf(a[5], q1.y, s);
        s = fmaf(a[6], q1.z, s);
        s = fmaf(a[7], q1.w, s);
        bb[k] = s;
    }
    __syncwarp();   // prior reads of this buffer are done
    float4* bw = reinterpret_cast<float4*>(bufbase + j * 8);
    bw[0] = make_float4(bb[0], bb[1], bb[2], bb[3]);
    bw[1] = make_float4(bb[4], bb[5], bb[6], bb[7]);
    __syncwarp();   // all 8 rows visible before gathering
#pragma unroll
    for (int k = 0; k < 8; k++) c[k] = 0.0f;
#pragma unroll
    for (int i = 0; i < 8; i++) {
        float qji = pQ[j * 9 + i];
        const float4* br = reinterpret_cast<const float4*>(bufbase + i * 8);
        float4 b0 = br[0];
        float4 b1 = br[1];
        c[0] = fmaf(qji, b0.x, c[0]);
        c[1] = fmaf(qji, b0.y, c[1]);
        c[2] = fmaf(qji, b0.z, c[2]);
        c[3] = fmaf(qji, b0.w, c[3]);
        c[4] = fmaf(qji, b1.x, c[4]);
        c[5] = fmaf(qji, b1.y, c[5]);
        c[6] = fmaf(qji, b1.z, c[6]);
        c[7] = fmaf(qji, b1.w, c[7]);
    }
}

__global__ void __launch_bounds__(128)
spdsru_main(const float* __restrict__ x,
            const float* __restrict__ states,
            float* __restrict__ out,
            float* __restrict__ outst) {
    __shared__ float sP[3 * 72];    // padded Qt | G | Qy (stride 9)
    __shared__ float sB[16 * 72];   // congruence scratch (4 warps * 4 groups)

    const int tid = threadIdx.x;
    if (tid < 64) {
        int r = tid >> 3, cc = tid & 7;
        const float* cf = reinterpret_cast<const float*>(c_params.Q4);
        sP[r * 9 + cc]       = cf[tid];         // Qt
        sP[72 + r * 9 + cc]  = cf[64 + tid];    // G
        sP[144 + r * 9 + cc] = cf[128 + tid];   // Qy
    }
    __syncthreads();

    const int grp = tid >> 3;            // 0..15
    const int j = tid & 7;
    const size_t b = (size_t)blockIdx.x * 16 + grp;
    float* bufbase = sB + grp * 72;

    // ---- load x row ----
    const float4* xp = reinterpret_cast<const float4*>(x + b * 64 + j * 8);
    float4 xa = xp[0], xb = xp[1];
    float xr[8] = {xa.x, xa.y, xa.z, xa.w, xb.x, xb.y, xb.z, xb.w};

    // ---- load state rows (register-resident), accumulate Yt in-flight ----
    float m[A_NUM][8];
    float yt[8];
#pragma unroll
    for (int k = 0; k < 8; k++) yt[k] = 0.0f;
#pragma unroll
    for (int a = 0; a < A_NUM; a++) {
        const float4* mp = reinterpret_cast<const float4*>(states + b * 320 + a * 64 + j * 8);
        float4 m0 = mp[0], m1 = mp[1];
        m[a][0] = m0.x; m[a][1] = m0.y; m[a][2] = m0.z; m[a][3] = m0.w;
        m[a][4] = m1.x; m[a][5] = m1.y; m[a][6] = m1.z; m[a][7] = m1.w;
        float wa = c_params.wr[a];
#pragma unroll
        for (int k = 0; k < 8; k++) yt[k] = fmaf(wa, m[a][k], yt[k]);
    }

    // ---- U = Qt*Xt*Qt^T ;  V = G*Yt*G^T  (G = Qt*Qr) ----
    float u[8], v[8];
    congruence8<0>(xr, sP, j, bufbase, u);
    congruence8<16>(yt, sP + 72, j, bufbase, v);

    // ---- Phit = (1-t)*U + t*V ----
    const float t = c_params.t;
    float phit[8];
#pragma unroll
    for (int k = 0; k < 8; k++) phit[k] = fmaf(t, v[k] - u[k], u[k]);

    // ---- Mt[a] = m + alpha*(Phit - m) ; St = sum ws[a]*Mt[a] ; write Mt ----
    const float alpha[A_NUM] = {0.01f, 0.25f, 0.5f, 0.9f, 0.99f};
    float st[8];
#pragma unroll
    for (int k = 0; k < 8; k++) st[k] = 0.0f;
#pragma unroll
    for (int a = 0; a < A_NUM; a++) {
        float mt[8];
        float wsa = c_params.ws[a];
#pragma unroll
        for (int k = 0; k < 8; k++) {
            mt[k] = fmaf(alpha[a], phit[k] - m[a][k], m[a][k]);
            st[k] = fmaf(wsa, mt[k], st[k]);
        }
        float4* op = reinterpret_cast<float4*>(outst + b * 320 + a * 64 + j * 8);
        op[0] = make_float4(mt[0], mt[1], mt[2], mt[3]);
        op[1] = make_float4(mt[4], mt[5], mt[6], mt[7]);
    }

    // ---- Ot = Qy * St * Qy^T ----
    float ot[8];
    congruence8<32>(st, sP + 144, j, bufbase, ot);
    float4* oo = reinterpret_cast<float4*>(out + b * 64 + j * 8);
    oo[0] = make_float4(ot[0], ot[1], ot[2], ot[3]);
    oo[1] = make_float4(ot[4], ot[5], ot[6], ot[7]);
}

extern "C" void kernel_launch(void* const* d_in, const int* in_sizes, int n_in,
                              void* d_out, int out_size) {
    const float* x      = (const float*)d_in[0];
    const float* states = (const float*)d_in[1];
    const float* kr     = (const float*)d_in[2];
    const float* kt     = (const float*)d_in[3];
    const float* kphi   = (const float*)d_in[4];
    const float* ks     = (const float*)d_in[5];
    const float* br     = (const float*)d_in[6];
    const float* bt     = (const float*)d_in[7];
    const float* by     = (const float*)d_in[8];

    const int batch = in_sizes[0] / 64;

    float* out   = (float*)d_out;
    float* outst = out + (size_t)batch * 64;

    // Device address of the __constant__ block — prologue writes it directly;
    // the main kernel's constant cache is loaded fresh at its own launch.
    void* csym = nullptr;
    cudaGetSymbolAddress(&csym, c_params);

    spdsru_prologue<<<1, 128>>>((Params*)csym, kr, kt, kphi, ks, br, bt, by);

    int blocks = batch / 16;
    spdsru_main<<<blocks, 128>>>(x, states, out, outst);
}